// round 5
// baseline (speedup 1.0000x reference)
#include <cuda_runtime.h>
#include <math.h>

// Problem shapes (fixed by the dataset)
#define Bv   32
#define Sv   4096
#define BSv  (Bv * Sv)      // 131072 rows
#define Dv   768            // K
#define Hv   1024           // N
#define BM   128
#define BN   128
#define BK   16
#define NT   (Hv / BN)      // 8 N-tiles
#define LDS_ 132            // padded smem stride (floats)

// ---------------- scratch (static device globals; no allocation) ----------
__device__ float g_mu[BSv];
__device__ float g_rstd[BSv];
__device__ float g_scores[BSv];
__device__ float g_part[NT * BSv];
__device__ float g_w1g[Hv * Dv];
__device__ float g_hbias[Hv];

// ---------------- packed f32x2 helpers ------------------------------------
__device__ __forceinline__ unsigned long long dupf(float a) {
    unsigned long long r;
    asm("mov.b64 %0, {%1, %1};" : "=l"(r) : "f"(a));
    return r;
}
__device__ __forceinline__ void ffma2(unsigned long long &c, unsigned long long a,
                                      unsigned long long b) {
    asm("fma.rn.f32x2 %0, %1, %2, %3;" : "=l"(c) : "l"(a), "l"(b), "l"(c));
}
__device__ __forceinline__ float2 unpk(unsigned long long v) {
    float2 f;
    asm("mov.b64 {%0, %1}, %2;" : "=f"(f.x), "=f"(f.y) : "l"(v));
    return f;
}

__device__ __forceinline__ float gelu_exact(float x) {
    return 0.5f * x * (1.0f + erff(x * 0.7071067811865475f));
}
__device__ __forceinline__ float softplusf(float x) {
    return fmaxf(x, 0.0f) + log1pf(expf(-fabsf(x)));
}

// ---------------- prep: fold ln_g into W1, (ln_b,b1) into hbias -----------
__global__ void prep_w1g(const float* __restrict__ w1, const float* __restrict__ lng) {
    int i = blockIdx.x * 256 + threadIdx.x;     // i < Hv*Dv
    int d = i % Dv;
    g_w1g[i] = w1[i] * lng[d];
}

__global__ void prep_hbias(const float* __restrict__ w1, const float* __restrict__ lnb,
                           const float* __restrict__ b1) {
    int h    = blockIdx.x * 8 + (threadIdx.x >> 5);
    int lane = threadIdx.x & 31;
    const float* wr = w1 + (size_t)h * Dv;
    float s = 0.0f;
    for (int d = lane; d < Dv; d += 32) s = fmaf(lnb[d], wr[d], s);
#pragma unroll
    for (int o = 16; o; o >>= 1) s += __shfl_xor_sync(0xffffffffu, s, o);
    if (lane == 0) g_hbias[h] = s + b1[h];
}

// ---------------- LayerNorm stats: one warp per row -----------------------
__global__ void ln_stats(const float* __restrict__ emb, const float* __restrict__ attn) {
    int row  = blockIdx.x * 8 + (threadIdx.x >> 5);
    int lane = threadIdx.x & 31;
    const float4* ev = (const float4*)(emb + (size_t)row * Dv);
    float at = attn[row];
    float s = 0.0f, ss = 0.0f;
#pragma unroll
    for (int j = 0; j < Dv / 128; j++) {              // 6 float4 per lane
        float4 v = ev[lane + 32 * j];
        float a = v.x * at, b = v.y * at, c = v.z * at, d = v.w * at;
        s += a + b + c + d;
        ss = fmaf(a, a, ss); ss = fmaf(b, b, ss);
        ss = fmaf(c, c, ss); ss = fmaf(d, d, ss);
    }
#pragma unroll
    for (int o = 16; o; o >>= 1) {
        s  += __shfl_xor_sync(0xffffffffu, s,  o);
        ss += __shfl_xor_sync(0xffffffffu, ss, o);
    }
    if (lane == 0) {
        float mu  = s * (1.0f / Dv);
        float var = fmaxf(ss * (1.0f / Dv) - mu * mu, 0.0f);
        g_mu[row]   = mu;
        g_rstd[row] = 1.0f / sqrtf(var + 1e-5f);
    }
}

// ---------------- fused LN + GEMM1 + GELU + w2-dot (partial scores) -------
#define STORE_TILES(S_)                                          \
    do {                                                         \
        As[S_][sg0 * 4 + 0][r0] = fmaf(eA0.x, sA0, ntA0);        \
        As[S_][sg0 * 4 + 1][r0] = fmaf(eA0.y, sA0, ntA0);        \
        As[S_][sg0 * 4 + 2][r0] = fmaf(eA0.z, sA0, ntA0);        \
        As[S_][sg0 * 4 + 3][r0] = fmaf(eA0.w, sA0, ntA0);        \
        As[S_][sg0 * 4 + 0][r1] = fmaf(eA1.x, sA1, ntA1);        \
        As[S_][sg0 * 4 + 1][r1] = fmaf(eA1.y, sA1, ntA1);        \
        As[S_][sg0 * 4 + 2][r1] = fmaf(eA1.z, sA1, ntA1);        \
        As[S_][sg0 * 4 + 3][r1] = fmaf(eA1.w, sA1, ntA1);        \
        Bs[S_][sg0 * 4 + 0][r0] = eB0.x;                         \
        Bs[S_][sg0 * 4 + 1][r0] = eB0.y;                         \
        Bs[S_][sg0 * 4 + 2][r0] = eB0.z;                         \
        Bs[S_][sg0 * 4 + 3][r0] = eB0.w;                         \
        Bs[S_][sg0 * 4 + 0][r1] = eB1.x;                         \
        Bs[S_][sg0 * 4 + 1][r1] = eB1.y;                         \
        Bs[S_][sg0 * 4 + 2][r1] = eB1.z;                         \
        Bs[S_][sg0 * 4 + 3][r1] = eB1.w;                         \
    } while (0)

__global__ void __launch_bounds__(256)
gemm_score_part(const float* __restrict__ emb, const float* __restrict__ attn,
                const float* __restrict__ w2) {
    __shared__ __align__(16) float As[2][BK][LDS_];
    __shared__ __align__(16) float Bs[2][BK][LDS_];
    __shared__ float srow[BM], trow[BM];

    int nt = blockIdx.x, mt = blockIdx.y;
    int m0 = mt * BM, n0 = nt * BN;
    int tid = threadIdx.x;
    int tx = tid & 15, ty = tid >> 4;

    if (tid < BM) {
        int m = m0 + tid;
        float rs = g_rstd[m];
        srow[tid] = attn[m] * rs;   // x_d = g_d*(e*s - t) + b_d  (g,b folded into W)
        trow[tid] = g_mu[m] * rs;
    }
    __syncthreads();

    // global-load mapping: 512 float4 per (A or B) tile, 2 per thread
    int r0 = tid >> 2, sg0 = tid & 3;
    int r1 = r0 + 64;
    float sA0 = srow[r0], ntA0 = -trow[r0];
    float sA1 = srow[r1], ntA1 = -trow[r1];
    const float4* ea0 = (const float4*)(emb + (size_t)(m0 + r0) * Dv) + sg0;
    const float4* ea1 = (const float4*)(emb + (size_t)(m0 + r1) * Dv) + sg0;
    const float4* wb0 = (const float4*)(g_w1g + (size_t)(n0 + r0) * Dv) + sg0;
    const float4* wb1 = (const float4*)(g_w1g + (size_t)(n0 + r1) * Dv) + sg0;

    unsigned long long acc[8][4];
#pragma unroll
    for (int i = 0; i < 8; i++)
#pragma unroll
        for (int j = 0; j < 4; j++) acc[i][j] = 0ull;

    float4 eA0 = ea0[0], eA1 = ea1[0], eB0 = wb0[0], eB1 = wb1[0];
    STORE_TILES(0);
    __syncthreads();

    int st = 0;
#pragma unroll 1
    for (int kt = 0; kt < Dv / BK; kt++) {
        if (kt + 1 < Dv / BK) {
            eA0 = ea0[(kt + 1) * 4];
            eA1 = ea1[(kt + 1) * 4];
            eB0 = wb0[(kt + 1) * 4];
            eB1 = wb1[(kt + 1) * 4];
        }
#pragma unroll
        for (int k = 0; k < BK; k++) {
            float4 a0 = *(const float4*)&As[st][k][ty * 8];
            float4 a1 = *(const float4*)&As[st][k][ty * 8 + 4];
            ulonglong2 b01 = *(const ulonglong2*)&Bs[st][k][tx * 8];
            ulonglong2 b23 = *(const ulonglong2*)&Bs[st][k][tx * 8 + 4];
            unsigned long long ad[8] = {dupf(a0.x), dupf(a0.y), dupf(a0.z), dupf(a0.w),
                                        dupf(a1.x), dupf(a1.y), dupf(a1.z), dupf(a1.w)};
#pragma unroll
            for (int i = 0; i < 8; i++) {
                ffma2(acc[i][0], ad[i], b01.x);
                ffma2(acc[i][1], ad[i], b01.y);
                ffma2(acc[i][2], ad[i], b23.x);
                ffma2(acc[i][3], ad[i], b23.y);
            }
        }
        if (kt + 1 < Dv / BK) {
            int ns = st ^ 1;
            STORE_TILES(ns);
            __syncthreads();
            st = ns;
        }
    }

    // epilogue: gelu(c + hbias) * w2, reduce over the 16 tx lanes per row
    int c0 = n0 + tx * 8;
    float bb[8], ww[8];
#pragma unroll
    for (int j = 0; j < 8; j++) { bb[j] = g_hbias[c0 + j]; ww[j] = w2[c0 + j]; }

#pragma unroll
    for (int i = 0; i < 8; i++) {
        float p = 0.0f;
#pragma unroll
        for (int jj = 0; jj < 4; jj++) {
            float2 v = unpk(acc[i][jj]);
            p += gelu_exact(v.x + bb[jj * 2]) * ww[jj * 2];
            p += gelu_exact(v.y + bb[jj * 2 + 1]) * ww[jj * 2 + 1];
        }
#pragma unroll
        for (int o = 8; o; o >>= 1) p += __shfl_xor_sync(0xffffffffu, p, o);
        if (tx == 0) g_part[nt * BSv + m0 + ty * 8 + i] = p;
    }
}

// ---------------- fixed-order partial reduction (deterministic) -----------
__global__ void score_reduce() {
    int i = blockIdx.x * 256 + threadIdx.x;
    float s = 0.0f;
#pragma unroll
    for (int nt = 0; nt < NT; nt++) s += g_part[nt * BSv + i];
    g_scores[i] = s;
}

// ---------------- entmax-1.5 over S via bisection on tau ------------------
// Solves sum(relu(x - tau)^2) = 1, identical root to the sort-based formula.
__global__ void __launch_bounds__(1024)
entmax_kernel(const float* __restrict__ attn, const float* __restrict__ b2,
              float* __restrict__ zout) {
    __shared__ float sx[Sv];
    __shared__ float red[33];
    int b = blockIdx.x, tid = threadIdx.x;
    int lane = tid & 31, wid = tid >> 5;
    float b2v = b2[0];
    const float* sc = g_scores + (size_t)b * Sv;
    const float* at = attn + (size_t)b * Sv;

    float loc[4], am[4];
    float mx = -3.4e38f;
#pragma unroll
    for (int j = 0; j < 4; j++) {
        int i = tid + j * 1024;
        float a = at[i]; am[j] = a;
        float v = (a == 0.0f) ? -1e9f : sc[i] + b2v;   // mask, +b2
        v *= 0.5f;                                      // entmax15 internal /2 (TAU=1)
        loc[j] = v;
        mx = fmaxf(mx, v);
    }
#pragma unroll
    for (int o = 16; o; o >>= 1) mx = fmaxf(mx, __shfl_xor_sync(0xffffffffu, mx, o));
    if (lane == 0) red[wid] = mx;
    __syncthreads();
    if (wid == 0) {
        float m = red[lane];
#pragma unroll
        for (int o = 16; o; o >>= 1) m = fmaxf(m, __shfl_xor_sync(0xffffffffu, m, o));
        if (lane == 0) red[32] = m;
    }
    __syncthreads();
    float xmax = red[32];
#pragma unroll
    for (int j = 0; j < 4; j++) sx[tid + j * 1024] = loc[j] - xmax;
    __syncthreads();

    float lo = -1.0f, hi = 0.0f;   // tau* in [xmax-1, xmax] (shifted coords)
    for (int it = 0; it < 30; it++) {
        float mid = 0.5f * (lo + hi);
        float s = 0.0f;
#pragma unroll
        for (int j = 0; j < 4; j++) {
            float d = fmaxf(sx[tid + j * 1024] - mid, 0.0f);
            s = fmaf(d, d, s);
        }
#pragma unroll
        for (int o = 16; o; o >>= 1) s += __shfl_xor_sync(0xffffffffu, s, o);
        __syncthreads();               // protect red[] reuse
        if (lane == 0) red[wid] = s;
        __syncthreads();
        if (wid == 0) {
            float t = red[lane];
#pragma unroll
            for (int o = 16; o; o >>= 1) t += __shfl_xor_sync(0xffffffffu, t, o);
            if (lane == 0) red[32] = t;
        }
        __syncthreads();
        float tot = red[32];
        if (tot >= 1.0f) lo = mid; else hi = mid;
    }
    float tau = 0.5f * (lo + hi);
#pragma unroll
    for (int j = 0; j < 4; j++) {
        int i = tid + j * 1024;
        float d = fmaxf(sx[i] - tau, 0.0f);
        zout[(size_t)b * Sv + i] = d * d * am[j];
    }
}

// ---------------- Kumaraswamy gate (g == h numerically) -------------------
__global__ void final_kernel(const float* __restrict__ attn, const float* __restrict__ u,
                             const float* __restrict__ b2, float* __restrict__ out,
                             int out_size) {
    int i = blockIdx.x * 256 + threadIdx.x;
    float a_ = attn[i];
    float sc = (a_ == 0.0f) ? -1e9f : g_scores[i] + b2[0];
    float z = out[i];                          // entmax result already in d_out
    float eff = sc + 2.0f * (2.0f * z - 1.0f); // COUPLING_K = 2
    float aa = softplusf(eff) + 1e-6f;
    float bbk = softplusf(-eff) + 1e-6f;
    float uc = fminf(fmaxf(u[i], 1e-6f), 1.0f - 1e-6f);
    float xk = powf(1.0f - powf(1.0f - uc, 1.0f / bbk), 1.0f / aa);
    float y = -0.1f + 1.2f * xk;               // L + (R-L)*xk
    float h = (fminf(fmaxf(y, 0.0f), 1.0f) > 0.5f) ? 1.0f : 0.0f;
    out[BSv + i] = h * a_;
    if (i == 0 && out_size >= 2 * BSv + 1) out[2 * BSv] = 0.0f;  // reg
}

// ---------------- launch ---------------------------------------------------
extern "C" void kernel_launch(void* const* d_in, const int* in_sizes, int n_in,
                              void* d_out, int out_size) {
    (void)in_sizes; (void)n_in;
    const float* emb  = (const float*)d_in[0];
    const float* attn = (const float*)d_in[1];
    const float* u    = (const float*)d_in[2];
    const float* lng  = (const float*)d_in[3];
    const float* lnb  = (const float*)d_in[4];
    const float* w1   = (const float*)d_in[5];
    const float* b1   = (const float*)d_in[6];
    const float* w2   = (const float*)d_in[7];
    const float* b2   = (const float*)d_in[8];
    float* out = (float*)d_out;

    prep_w1g<<<(Hv * Dv) / 256, 256>>>(w1, lng);
    prep_hbias<<<Hv / 8, 256>>>(w1, lnb, b1);
    ln_stats<<<BSv / 8, 256>>>(emb, attn);
    gemm_score_part<<<dim3(NT, BSv / BM), 256>>>(emb, attn, w2);
    score_reduce<<<BSv / 256, 256>>>();
    entmax_kernel<<<Bv, 1024>>>(attn, b2, out);
    final_kernel<<<BSv / 256, 256>>>(attn, u, b2, out, out_size);
}

// round 6
// speedup vs baseline: 1.1293x; 1.1293x over previous
#include <cuda_runtime.h>
#include <math.h>

// Problem shapes (fixed by the dataset)
#define Bv   32
#define Sv   4096
#define BSv  (Bv * Sv)      // 131072 rows
#define Dv   768            // K
#define Hv   1024           // N
#define BM   256
#define BN   128
#define BK   16
#define NT   (Hv / BN)      // 8 N-tiles
#define LDA_ 260            // padded smem stride for A (floats)
#define LDB_ 132            // padded smem stride for B (floats)

#define SMEM_FLOATS (2 * BK * LDA_ + 2 * BK * LDB_ + 2 * BM)
#define SMEM_BYTES  (SMEM_FLOATS * 4)

// ---------------- scratch (static device globals; no allocation) ----------
__device__ float g_mu[BSv];
__device__ float g_rstd[BSv];
__device__ float g_scores[BSv];
__device__ float g_part[NT * BSv];
__device__ float g_w1g[Hv * Dv];
__device__ float g_hbias[Hv];

// ---------------- packed f32x2 helpers ------------------------------------
__device__ __forceinline__ unsigned long long dupf(float a) {
    unsigned long long r;
    asm("mov.b64 %0, {%1, %1};" : "=l"(r) : "f"(a));
    return r;
}
__device__ __forceinline__ void ffma2(unsigned long long &c, unsigned long long a,
                                      unsigned long long b) {
    asm("fma.rn.f32x2 %0, %1, %2, %3;" : "=l"(c) : "l"(a), "l"(b), "l"(c));
}
__device__ __forceinline__ float2 unpk(unsigned long long v) {
    float2 f;
    asm("mov.b64 {%0, %1}, %2;" : "=f"(f.x), "=f"(f.y) : "l"(v));
    return f;
}

__device__ __forceinline__ float gelu_exact(float x) {
    return 0.5f * x * (1.0f + erff(x * 0.7071067811865475f));
}
__device__ __forceinline__ float softplusf(float x) {
    return fmaxf(x, 0.0f) + log1pf(expf(-fabsf(x)));
}

// ---------------- prep: fold ln_g into W1, (ln_b,b1) into hbias -----------
__global__ void prep_w1g(const float* __restrict__ w1, const float* __restrict__ lng) {
    int i = blockIdx.x * 256 + threadIdx.x;     // i < Hv*Dv
    int d = i % Dv;
    g_w1g[i] = w1[i] * lng[d];
}

__global__ void prep_hbias(const float* __restrict__ w1, const float* __restrict__ lnb,
                           const float* __restrict__ b1) {
    int h    = blockIdx.x * 8 + (threadIdx.x >> 5);
    int lane = threadIdx.x & 31;
    const float* wr = w1 + (size_t)h * Dv;
    float s = 0.0f;
    for (int d = lane; d < Dv; d += 32) s = fmaf(lnb[d], wr[d], s);
#pragma unroll
    for (int o = 16; o; o >>= 1) s += __shfl_xor_sync(0xffffffffu, s, o);
    if (lane == 0) g_hbias[h] = s + b1[h];
}

// ---------------- LayerNorm stats: one warp per row -----------------------
__global__ void ln_stats(const float* __restrict__ emb, const float* __restrict__ attn) {
    int row  = blockIdx.x * 8 + (threadIdx.x >> 5);
    int lane = threadIdx.x & 31;
    const float4* ev = (const float4*)(emb + (size_t)row * Dv);
    float at = attn[row];
    float s = 0.0f, ss = 0.0f;
#pragma unroll
    for (int j = 0; j < Dv / 128; j++) {              // 6 float4 per lane
        float4 v = ev[lane + 32 * j];
        float a = v.x * at, b = v.y * at, c = v.z * at, d = v.w * at;
        s += a + b + c + d;
        ss = fmaf(a, a, ss); ss = fmaf(b, b, ss);
        ss = fmaf(c, c, ss); ss = fmaf(d, d, ss);
    }
#pragma unroll
    for (int o = 16; o; o >>= 1) {
        s  += __shfl_xor_sync(0xffffffffu, s,  o);
        ss += __shfl_xor_sync(0xffffffffu, ss, o);
    }
    if (lane == 0) {
        float mu  = s * (1.0f / Dv);
        float var = fmaxf(ss * (1.0f / Dv) - mu * mu, 0.0f);
        g_mu[row]   = mu;
        g_rstd[row] = 1.0f / sqrtf(var + 1e-5f);
    }
}

// ---------------- fused LN + GEMM1 + GELU + w2-dot (partial scores) -------
// 256x128x16 tiles, 256 threads, 16x8 micro-tile held as row-paired f32x2.
// A fragment loads straight from smem as ulonglong2 (rows paired) -> no dup.

#define AS(S_, K_, M_) As_[((S_) * BK + (K_)) * LDA_ + (M_)]
#define BS(S_, K_, M_) Bs_[((S_) * BK + (K_)) * LDB_ + (M_)]

#define STORE_TILES(S_)                                                   \
    do {                                                                  \
        _Pragma("unroll")                                                 \
        for (int c = 0; c < 4; c++) {                                     \
            AS(S_, sg * 4 + 0, r + 64 * c) = fmaf(pA[c].x, sA[c], ntA[c]);\
            AS(S_, sg * 4 + 1, r + 64 * c) = fmaf(pA[c].y, sA[c], ntA[c]);\
            AS(S_, sg * 4 + 2, r + 64 * c) = fmaf(pA[c].z, sA[c], ntA[c]);\
            AS(S_, sg * 4 + 3, r + 64 * c) = fmaf(pA[c].w, sA[c], ntA[c]);\
        }                                                                 \
        _Pragma("unroll")                                                 \
        for (int c = 0; c < 2; c++) {                                     \
            BS(S_, sg * 4 + 0, r + 64 * c) = pB[c].x;                     \
            BS(S_, sg * 4 + 1, r + 64 * c) = pB[c].y;                     \
            BS(S_, sg * 4 + 2, r + 64 * c) = pB[c].z;                     \
            BS(S_, sg * 4 + 3, r + 64 * c) = pB[c].w;                     \
        }                                                                 \
    } while (0)

__global__ void __launch_bounds__(256, 1)
gemm_score_part(const float* __restrict__ emb, const float* __restrict__ attn,
                const float* __restrict__ w2) {
    extern __shared__ float smem_[];
    float* As_  = smem_;
    float* Bs_  = smem_ + 2 * BK * LDA_;
    float* srow = smem_ + 2 * BK * LDA_ + 2 * BK * LDB_;
    float* trow = srow + BM;

    int nt = blockIdx.x, mt = blockIdx.y;
    int m0 = mt * BM, n0 = nt * BN;
    int tid = threadIdx.x;
    int tx = tid & 15, tyy = tid >> 4;

    {   // LN row scale/shift: x_d = g_d*(e*s - t) + b_d  (g,b folded into W1)
        int m = m0 + tid;
        float rs = g_rstd[m];
        srow[tid] = attn[m] * rs;
        trow[tid] = g_mu[m] * rs;
    }
    __syncthreads();

    // global-load mapping: A tile 1024 float4 (4/thread), B tile 512 (2/thread)
    int r = tid >> 2, sg = tid & 3;
    float sA[4], ntA[4];
#pragma unroll
    for (int c = 0; c < 4; c++) { sA[c] = srow[r + 64 * c]; ntA[c] = -trow[r + 64 * c]; }

    const float4* ea[4];
    const float4* wb[2];
#pragma unroll
    for (int c = 0; c < 4; c++)
        ea[c] = (const float4*)(emb + (size_t)(m0 + r + 64 * c) * Dv) + sg;
#pragma unroll
    for (int c = 0; c < 2; c++)
        wb[c] = (const float4*)(g_w1g + (size_t)(n0 + r + 64 * c) * Dv) + sg;

    unsigned long long acc[8][8];
#pragma unroll
    for (int p = 0; p < 8; p++)
#pragma unroll
        for (int j = 0; j < 8; j++) acc[p][j] = 0ull;

    float4 pA[4], pB[2];
#pragma unroll
    for (int c = 0; c < 4; c++) pA[c] = ea[c][0];
#pragma unroll
    for (int c = 0; c < 2; c++) pB[c] = wb[c][0];
    STORE_TILES(0);
    __syncthreads();

    int st = 0;
#pragma unroll 1
    for (int kt = 0; kt < Dv / BK; kt++) {
        if (kt + 1 < Dv / BK) {
#pragma unroll
            for (int c = 0; c < 4; c++) pA[c] = ea[c][(kt + 1) * 4];
#pragma unroll
            for (int c = 0; c < 2; c++) pB[c] = wb[c][(kt + 1) * 4];
        }
#pragma unroll
        for (int k = 0; k < BK; k++) {
            // A: 16 rows as 8 row-pairs (f32x2), straight vector loads
            ulonglong2 a01 = *(const ulonglong2*)&AS(st, k, tyy * 16);
            ulonglong2 a23 = *(const ulonglong2*)&AS(st, k, tyy * 16 + 4);
            ulonglong2 a45 = *(const ulonglong2*)&AS(st, k, tyy * 16 + 8);
            ulonglong2 a67 = *(const ulonglong2*)&AS(st, k, tyy * 16 + 12);
            unsigned long long ap[8] = {a01.x, a01.y, a23.x, a23.y,
                                        a45.x, a45.y, a67.x, a67.y};
            // B: 8 cols, duplicated into f32x2
            float4 bv0 = *(const float4*)&BS(st, k, tx * 8);
            float4 bv1 = *(const float4*)&BS(st, k, tx * 8 + 4);
            unsigned long long bd[8] = {dupf(bv0.x), dupf(bv0.y), dupf(bv0.z), dupf(bv0.w),
                                        dupf(bv1.x), dupf(bv1.y), dupf(bv1.z), dupf(bv1.w)};
#pragma unroll
            for (int p = 0; p < 8; p++)
#pragma unroll
                for (int j = 0; j < 8; j++) ffma2(acc[p][j], ap[p], bd[j]);
        }
        if (kt + 1 < Dv / BK) {
            int ns = st ^ 1;
            STORE_TILES(ns);
            __syncthreads();
            st = ns;
        }
    }

    // epilogue: gelu(c + hbias) * w2, reduce over the 16 tx lanes per row.
    // acc[p][j] holds rows (2p, 2p+1) in (x, y), column tx*8+j.
    int c0 = n0 + tx * 8;
    float bb[8], ww[8];
#pragma unroll
    for (int j = 0; j < 8; j++) { bb[j] = g_hbias[c0 + j]; ww[j] = w2[c0 + j]; }

#pragma unroll
    for (int p = 0; p < 8; p++) {
        float p0 = 0.0f, p1 = 0.0f;
#pragma unroll
        for (int j = 0; j < 8; j++) {
            float2 v = unpk(acc[p][j]);
            p0 += gelu_exact(v.x + bb[j]) * ww[j];
            p1 += gelu_exact(v.y + bb[j]) * ww[j];
        }
#pragma unroll
        for (int o = 8; o; o >>= 1) {
            p0 += __shfl_xor_sync(0xffffffffu, p0, o);
            p1 += __shfl_xor_sync(0xffffffffu, p1, o);
        }
        if (tx == 0) {
            int row = m0 + tyy * 16 + 2 * p;
            g_part[nt * BSv + row]     = p0;
            g_part[nt * BSv + row + 1] = p1;
        }
    }
}

// ---------------- fixed-order partial reduction (deterministic) -----------
__global__ void score_reduce() {
    int i = blockIdx.x * 256 + threadIdx.x;
    float s = 0.0f;
#pragma unroll
    for (int nt = 0; nt < NT; nt++) s += g_part[nt * BSv + i];
    g_scores[i] = s;
}

// ---------------- entmax-1.5 over S via bisection on tau ------------------
// Solves sum(relu(x - tau)^2) = 1, identical root to the sort-based formula.
__global__ void __launch_bounds__(1024)
entmax_kernel(const float* __restrict__ attn, const float* __restrict__ b2,
              float* __restrict__ zout) {
    __shared__ float sx[Sv];
    __shared__ float red[33];
    int b = blockIdx.x, tid = threadIdx.x;
    int lane = tid & 31, wid = tid >> 5;
    float b2v = b2[0];
    const float* sc = g_scores + (size_t)b * Sv;
    const float* at = attn + (size_t)b * Sv;

    float loc[4], am[4];
    float mx = -3.4e38f;
#pragma unroll
    for (int j = 0; j < 4; j++) {
        int i = tid + j * 1024;
        float a = at[i]; am[j] = a;
        float v = (a == 0.0f) ? -1e9f : sc[i] + b2v;   // mask, +b2
        v *= 0.5f;                                      // entmax15 internal /2 (TAU=1)
        loc[j] = v;
        mx = fmaxf(mx, v);
    }
#pragma unroll
    for (int o = 16; o; o >>= 1) mx = fmaxf(mx, __shfl_xor_sync(0xffffffffu, mx, o));
    if (lane == 0) red[wid] = mx;
    __syncthreads();
    if (wid == 0) {
        float m = red[lane];
#pragma unroll
        for (int o = 16; o; o >>= 1) m = fmaxf(m, __shfl_xor_sync(0xffffffffu, m, o));
        if (lane == 0) red[32] = m;
    }
    __syncthreads();
    float xmax = red[32];
#pragma unroll
    for (int j = 0; j < 4; j++) sx[tid + j * 1024] = loc[j] - xmax;
    __syncthreads();

    float lo = -1.0f, hi = 0.0f;   // tau* in [xmax-1, xmax] (shifted coords)
    for (int it = 0; it < 30; it++) {
        float mid = 0.5f * (lo + hi);
        float s = 0.0f;
#pragma unroll
        for (int j = 0; j < 4; j++) {
            float d = fmaxf(sx[tid + j * 1024] - mid, 0.0f);
            s = fmaf(d, d, s);
        }
#pragma unroll
        for (int o = 16; o; o >>= 1) s += __shfl_xor_sync(0xffffffffu, s, o);
        __syncthreads();               // protect red[] reuse
        if (lane == 0) red[wid] = s;
        __syncthreads();
        if (wid == 0) {
            float t = red[lane];
#pragma unroll
            for (int o = 16; o; o >>= 1) t += __shfl_xor_sync(0xffffffffu, t, o);
            if (lane == 0) red[32] = t;
        }
        __syncthreads();
        float tot = red[32];
        if (tot >= 1.0f) lo = mid; else hi = mid;
    }
    float tau = 0.5f * (lo + hi);
#pragma unroll
    for (int j = 0; j < 4; j++) {
        int i = tid + j * 1024;
        float d = fmaxf(sx[i] - tau, 0.0f);
        zout[(size_t)b * Sv + i] = d * d * am[j];
    }
}

// ---------------- Kumaraswamy gate (g == h numerically) -------------------
__global__ void final_kernel(const float* __restrict__ attn, const float* __restrict__ u,
                             const float* __restrict__ b2, float* __restrict__ out,
                             int out_size) {
    int i = blockIdx.x * 256 + threadIdx.x;
    float a_ = attn[i];
    float sc = (a_ == 0.0f) ? -1e9f : g_scores[i] + b2[0];
    float z = out[i];                          // entmax result already in d_out
    float eff = sc + 2.0f * (2.0f * z - 1.0f); // COUPLING_K = 2
    float aa = softplusf(eff) + 1e-6f;
    float bbk = softplusf(-eff) + 1e-6f;
    float uc = fminf(fmaxf(u[i], 1e-6f), 1.0f - 1e-6f);
    float xk = powf(1.0f - powf(1.0f - uc, 1.0f / bbk), 1.0f / aa);
    float y = -0.1f + 1.2f * xk;               // L + (R-L)*xk
    float h = (fminf(fmaxf(y, 0.0f), 1.0f) > 0.5f) ? 1.0f : 0.0f;
    out[BSv + i] = h * a_;
    if (i == 0 && out_size >= 2 * BSv + 1) out[2 * BSv] = 0.0f;  // reg
}

// ---------------- launch ---------------------------------------------------
extern "C" void kernel_launch(void* const* d_in, const int* in_sizes, int n_in,
                              void* d_out, int out_size) {
    (void)in_sizes; (void)n_in;
    const float* emb  = (const float*)d_in[0];
    const float* attn = (const float*)d_in[1];
    const float* u    = (const float*)d_in[2];
    const float* lng  = (const float*)d_in[3];
    const float* lnb  = (const float*)d_in[4];
    const float* w1   = (const float*)d_in[5];
    const float* b1   = (const float*)d_in[6];
    const float* w2   = (const float*)d_in[7];
    const float* b2   = (const float*)d_in[8];
    float* out = (float*)d_out;

    cudaFuncSetAttribute(gemm_score_part,
                         cudaFuncAttributeMaxDynamicSharedMemorySize, SMEM_BYTES);

    prep_w1g<<<(Hv * Dv) / 256, 256>>>(w1, lng);
    prep_hbias<<<Hv / 8, 256>>>(w1, lnb, b1);
    ln_stats<<<BSv / 8, 256>>>(emb, attn);
    gemm_score_part<<<dim3(NT, BSv / BM), 256, SMEM_BYTES>>>(emb, attn, w2);
    score_reduce<<<BSv / 256, 256>>>();
    entmax_kernel<<<Bv, 1024>>>(attn, b2, out);
    final_kernel<<<BSv / 256, 256>>>(attn, u, b2, out, out_size);
}